// round 17
// baseline (speedup 1.0000x reference)
#include <cuda_runtime.h>
#include <cuda_fp16.h>
#include <cstdint>
#include <math.h>

// Problem constants
#define BATCH 2
#define SEQ   2048
#define CMODEL 1024
#define NHEAD 16
#define HDIM  64
#define MROWS (BATCH * SEQ)   // 4096

// ---------------------------------------------------------------------------
// Scratch
// ---------------------------------------------------------------------------
__device__ __half g_qh[MROWS * CMODEL];
__device__ __half g_kh[MROWS * CMODEL];
__device__ __half g_vh[MROWS * CMODEL];
__device__ __half g_attnh[MROWS * CMODEL];
__device__ __half g_xh[MROWS * CMODEL];
__device__ __half g_wh[4 * CMODEL * CMODEL];

// ---------------------------------------------------------------------------
// Helpers
// ---------------------------------------------------------------------------
__device__ __forceinline__ uint32_t smem_u32(const void* p) {
    uint32_t a;
    asm("{ .reg .u64 t; cvta.to.shared.u64 t, %1; cvt.u32.u64 %0, t; }" : "=r"(a) : "l"(p));
    return a;
}
__device__ __forceinline__ void cp_async16(uint32_t s, const void* g) {
    asm volatile("cp.async.ca.shared.global [%0], [%1], 16;" :: "r"(s), "l"(g));
}
#define CP_COMMIT()  asm volatile("cp.async.commit_group;" ::: "memory")
#define CP_WAIT(N)   asm volatile("cp.async.wait_group %0;" :: "n"(N) : "memory")

__device__ __forceinline__ void mma_f16(float (&d)[4], const uint32_t (&a)[4],
                                        const uint32_t (&b)[2]) {
    asm volatile(
        "mma.sync.aligned.m16n8k16.row.col.f32.f16.f16.f32 "
        "{%0,%1,%2,%3}, {%4,%5,%6,%7}, {%8,%9}, {%0,%1,%2,%3};"
        : "+f"(d[0]), "+f"(d[1]), "+f"(d[2]), "+f"(d[3])
        : "r"(a[0]), "r"(a[1]), "r"(a[2]), "r"(a[3]), "r"(b[0]), "r"(b[1]));
}
__device__ __forceinline__ void ldsm_x4(uint32_t& r0, uint32_t& r1, uint32_t& r2,
                                        uint32_t& r3, uint32_t addr) {
    asm volatile("ldmatrix.sync.aligned.m8n8.x4.shared.b16 {%0,%1,%2,%3}, [%4];"
                 : "=r"(r0), "=r"(r1), "=r"(r2), "=r"(r3) : "r"(addr));
}
__device__ __forceinline__ void ldsm_x2_trans(uint32_t& r0, uint32_t& r1, uint32_t addr) {
    asm volatile("ldmatrix.sync.aligned.m8n8.x2.trans.shared.b16 {%0,%1}, [%2];"
                 : "=r"(r0), "=r"(r1) : "r"(addr));
}

// ---------------------------------------------------------------------------
// Fused prepass: fp32 -> fp16, one launch
// ---------------------------------------------------------------------------
__global__ void to_half_all(const float* __restrict__ x,
                            const float* __restrict__ wq,
                            const float* __restrict__ wk,
                            const float* __restrict__ wv,
                            const float* __restrict__ wo,
                            __half* __restrict__ xh,
                            __half* __restrict__ wh) {
    const long long nx = (long long)MROWS * CMODEL;
    const long long nw = (long long)CMODEL * CMODEL;
    long long i = (long long)(blockIdx.x * 256 + threadIdx.x) * 8;
    if (i >= nx + 4 * nw) return;

    const float* src;
    __half* dst;
    long long off;
    if (i < nx) {
        src = x; dst = xh; off = i;
    } else {
        long long j = i - nx;
        int s = (int)(j / nw);
        off = j - (long long)s * nw;
        src = (s == 0) ? wq : (s == 1) ? wk : (s == 2) ? wv : wo;
        dst = wh + (size_t)s * nw;
    }
    float4 v0 = *reinterpret_cast<const float4*>(src + off);
    float4 v1 = *reinterpret_cast<const float4*>(src + off + 4);
    __half2 h[4];
    h[0] = __floats2half2_rn(v0.x, v0.y);
    h[1] = __floats2half2_rn(v0.z, v0.w);
    h[2] = __floats2half2_rn(v1.x, v1.y);
    h[3] = __floats2half2_rn(v1.z, v1.w);
    *reinterpret_cast<uint2*>(dst + off)     = *reinterpret_cast<uint2*>(&h[0]);
    *reinterpret_cast<uint2*>(dst + off + 4) = *reinterpret_cast<uint2*>(&h[2]);
}

// ---------------------------------------------------------------------------
// FP16 GEMM: C = A * W^T. CTA 128x128, 128 threads = 4 warps in 2(M) x 2(N);
// warp tile 64x64. BK=64 (4 k16-steps), 3-stage pipeline, ldmatrix,
// one barrier per K-tile, 2 CTAs/SM.
// ---------------------------------------------------------------------------
#define BK 64
#define KSTH 72                        // padded row stride (halves)
#define ATH (128 * KSTH)
#define WTH (128 * KSTH)
#define STAGEH (ATH + WTH)
#define GH_SMEM_BYTES (3 * STAGEH * 2)   // 110592

__device__ __forceinline__ void gemm_body_h(const __half* __restrict__ A,
                                            const __half* __restrict__ W,
                                            float* __restrict__ Cf,
                                            __half* __restrict__ Ch,
                                            const float* __restrict__ freqs,
                                            int m0, int n0, bool rope,
                                            __half* smem) {
    const int K = CMODEL, N = CMODEL;
    __half* As[3] = { smem, smem + STAGEH, smem + 2 * STAGEH };
    __half* Ws[3] = { smem + ATH, smem + STAGEH + ATH, smem + 2 * STAGEH + ATH };

    const int tid  = threadIdx.x;
    const int lane = tid & 31;
    const int wid  = tid >> 5;       // 0..3
    const int g    = lane >> 2;
    const int tg   = lane & 3;
    const int wm   = (wid & 1) * 64;
    const int wn   = (wid >> 1) * 64;

    // ldmatrix lane mappings
    const int arow = (lane & 7) + ((lane >> 3) & 1) * 8;   // A-type x4
    const int acol = (lane >> 4) * 8;
    const int brow = (lane & 7) + ((lane >> 4) & 1) * 8;   // B-type x4 (nt pair)
    const int bcol = ((lane >> 3) & 1) * 8;

    uint32_t aoff[4], boff[4];
#pragma unroll
    for (int mt = 0; mt < 4; mt++)
        aoff[mt] = ((wm + mt * 16 + arow) * KSTH + acol) * 2;
#pragma unroll
    for (int j = 0; j < 4; j++)
        boff[j] = (ATH + (wn + j * 16 + brow) * KSTH + bcol) * 2;

    float acc[4][8][4];
#pragma unroll
    for (int mt = 0; mt < 4; mt++)
#pragma unroll
        for (int nt = 0; nt < 8; nt++)
#pragma unroll
            for (int r = 0; r < 4; r++) acc[mt][nt][r] = 0.0f;

    const int ntiles = K / BK;   // 16

    // loaders (128 threads): A tile 1024 16B-chunks -> 8/thread; W same
    auto load_tile = [&](int kt, int stg) {
        const int ko = kt * BK;
#pragma unroll
        for (int i = 0; i < 8; i++) {
            const int f = tid + 128 * i;       // 0..1023
            const int row = f >> 3;            // 0..127
            const int c8 = (f & 7) * 8;
            cp_async16(smem_u32(&As[stg][row * KSTH + c8]),
                       &A[(size_t)(m0 + row) * K + ko + c8]);
            cp_async16(smem_u32(&Ws[stg][row * KSTH + c8]),
                       &W[(size_t)(n0 + row) * K + ko + c8]);
        }
    };

    load_tile(0, 0);
    CP_COMMIT();
    load_tile(1, 1);
    CP_COMMIT();

    const uint32_t sbase = smem_u32(smem);

    for (int kt = 0; kt < ntiles; kt++) {
        if (kt + 1 < ntiles) { CP_WAIT(1); } else { CP_WAIT(0); }
        __syncthreads();
        if (kt + 2 < ntiles) {
            load_tile(kt + 2, (kt + 2) % 3);
            CP_COMMIT();
        }

        const uint32_t stg = sbase + (uint32_t)((kt % 3) * STAGEH * 2);
#pragma unroll
        for (int ks = 0; ks < 4; ks++) {
            const uint32_t kb = (uint32_t)(ks * 32);   // 16 halves = 32 bytes
            uint32_t a[4][4];
#pragma unroll
            for (int mt = 0; mt < 4; mt++)
                ldsm_x4(a[mt][0], a[mt][1], a[mt][2], a[mt][3], stg + aoff[mt] + kb);
            uint32_t b[8][2];
#pragma unroll
            for (int j = 0; j < 4; j++)
                ldsm_x4(b[2 * j][0], b[2 * j][1], b[2 * j + 1][0], b[2 * j + 1][1],
                        stg + boff[j] + kb);
#pragma unroll
            for (int mt = 0; mt < 4; mt++)
#pragma unroll
                for (int nt = 0; nt < 8; nt++)
                    mma_f16(acc[mt][nt], a[mt], b[nt]);
        }
        // no trailing barrier: next iteration's top barrier provides the
        // cross-warp ordering (3-stage ring, prefetch distance 2)
    }

    // epilogue
#pragma unroll
    for (int mt = 0; mt < 4; mt++) {
        const int row = m0 + wm + mt * 16 + g;
        const int t0 = row & (SEQ - 1);
        const int t1 = (row + 8) & (SEQ - 1);
#pragma unroll
        for (int nt = 0; nt < 8; nt++) {
            const int col = n0 + wn + nt * 8 + 2 * tg;
            float2 v0 = make_float2(acc[mt][nt][0], acc[mt][nt][1]);
            float2 v1 = make_float2(acc[mt][nt][2], acc[mt][nt][3]);
            if (rope) {
                const int fo = (col & 62);
                float cc0 = freqs[t0 * HDIM + fo], ss0 = freqs[t0 * HDIM + fo + 1];
                float cc1 = freqs[t1 * HDIM + fo], ss1 = freqs[t1 * HDIM + fo + 1];
                v0 = make_float2(v0.x * cc0 - v0.y * ss0, v0.x * ss0 + v0.y * cc0);
                v1 = make_float2(v1.x * cc1 - v1.y * ss1, v1.x * ss1 + v1.y * cc1);
            }
            if (Ch) {
                *reinterpret_cast<__half2*>(&Ch[(size_t)row * N + col]) =
                    __floats2half2_rn(v0.x, v0.y);
                *reinterpret_cast<__half2*>(&Ch[(size_t)(row + 8) * N + col]) =
                    __floats2half2_rn(v1.x, v1.y);
            } else {
                *reinterpret_cast<float2*>(&Cf[(size_t)row * N + col]) = v0;
                *reinterpret_cast<float2*>(&Cf[(size_t)(row + 8) * N + col]) = v1;
            }
        }
    }
}

__global__ __launch_bounds__(128, 2) void gemm_qkv(const __half* __restrict__ xh,
                                                   const __half* __restrict__ wh,
                                                   __half* __restrict__ q,
                                                   __half* __restrict__ k,
                                                   __half* __restrict__ v,
                                                   const float* __restrict__ freqs) {
    extern __shared__ __half smemh[];
    const int wsel = blockIdx.x >> 3;
    const int n0 = (blockIdx.x & 7) * 128;
    const int m0 = blockIdx.y * 128;
    const __half* W = wh + (size_t)wsel * CMODEL * CMODEL;
    __half* C = (wsel == 0) ? q : (wsel == 1) ? k : v;
    gemm_body_h(xh, W, nullptr, C, freqs, m0, n0, wsel < 2, smemh);
}

__global__ __launch_bounds__(128, 2) void gemm_proj(const __half* __restrict__ attnh,
                                                    const __half* __restrict__ wh,
                                                    float* __restrict__ C) {
    extern __shared__ __half smemh[];
    gemm_body_h(attnh, wh + (size_t)3 * CMODEL * CMODEL, C, nullptr, nullptr,
                blockIdx.y * 128, blockIdx.x * 128, false, smemh);
}

// ---------------------------------------------------------------------------
// FP16 flash-attention, causal. 3-stage pipeline, ldmatrix fragments,
// one barrier per tile, 2 CTAs/SM. (unchanged from R16)
// ---------------------------------------------------------------------------
#define VROW 72
#define HTILE (64 * VROW)
#define HSMEM_BYTES (6 * HTILE * 2 + 128 * VROW * 2)   // 73728

__global__ __launch_bounds__(256, 2) void flash_attn_mma(const __half* __restrict__ Q,
                                                         const __half* __restrict__ K,
                                                         const __half* __restrict__ V,
                                                         __half* __restrict__ O) {
    extern __shared__ __half smh[];
    __half* Ps = smh + 6 * HTILE;        // [128][VROW]

    const int tid  = threadIdx.x;
    const int lane = tid & 31;
    const int wid  = tid >> 5;
    const int g    = lane >> 2;
    const int tg   = lane & 3;

    const int qb = (int)gridDim.x - 1 - (int)blockIdx.x;
    const int h  = blockIdx.y;
    const int b  = blockIdx.z;
    const int q0 = qb * 128;
    const int wrow = wid * 16;
    const int r0g = q0 + wrow + g;
    const int r1g = r0g + 8;

    const int arow = (lane & 7) + ((lane >> 3) & 1) * 8;
    const int acol = (lane >> 4) * 8;
    const int brow = (lane & 7) + ((lane >> 4) & 1) * 8;
    const int bcol = ((lane >> 3) & 1) * 8;

    const __half2 s2 = __half2half2(__float2half(0.125f));
    uint32_t qf[4][4];
    {
        const __half* q0p = Q + (((size_t)b * SEQ + r0g) * NHEAD + h) * HDIM;
        const __half* q1p = Q + (((size_t)b * SEQ + r1g) * NHEAD + h) * HDIM;
#pragma unroll
        for (int ks = 0; ks < 4; ks++) {
            const int kc = ks * 16 + 2 * tg;
            __half2 h0 = __hmul2(*reinterpret_cast<const __half2*>(q0p + kc), s2);
            __half2 h1 = __hmul2(*reinterpret_cast<const __half2*>(q1p + kc), s2);
            __half2 h2 = __hmul2(*reinterpret_cast<const __half2*>(q0p + kc + 8), s2);
            __half2 h3 = __hmul2(*reinterpret_cast<const __half2*>(q1p + kc + 8), s2);
            qf[ks][0] = *reinterpret_cast<uint32_t*>(&h0);
            qf[ks][1] = *reinterpret_cast<uint32_t*>(&h1);
            qf[ks][2] = *reinterpret_cast<uint32_t*>(&h2);
            qf[ks][3] = *reinterpret_cast<uint32_t*>(&h3);
        }
    }

    float of[8][4];
#pragma unroll
    for (int nt = 0; nt < 8; nt++)
#pragma unroll
        for (int r = 0; r < 4; r++) of[nt][r] = 0.0f;
    float mrow[2] = { -1e30f, -1e30f };
    float lrow[2] = { 0.0f, 0.0f };

    const int ntiles = (q0 + 128) / 64;

    const uint32_t ks0 = smem_u32(smh);
    const uint32_t stageB = 2 * HTILE * 2;
    const uint32_t psbase = smem_u32(Ps);

    auto prefetch = [&](int t, int s) {
        const int kt = t * 64;
#pragma unroll
        for (int i = 0; i < 2; i++) {
            const int f = tid + 256 * i;
            const int row = f >> 3;
            const int c8 = (f & 7) * 8;
            const size_t gsrc = (((size_t)b * SEQ + kt + row) * NHEAD + h) * HDIM + c8;
            const uint32_t soff = s * stageB + (row * VROW + c8) * 2;
            cp_async16(ks0 + soff, &K[gsrc]);
            cp_async16(ks0 + soff + HTILE * 2, &V[gsrc]);
        }
    };

    prefetch(0, 0);
    CP_COMMIT();
    prefetch(1, 1);
    CP_COMMIT();

    for (int t = 0; t < ntiles; t++) {
        const int kt = t * 64;
        if (t + 1 < ntiles) { CP_WAIT(1); } else { CP_WAIT(0); }
        __syncthreads();
        if (t + 2 < ntiles) {
            prefetch(t + 2, (t + 2) % 3);
            CP_COMMIT();
        }

        const bool skip = kt > q0 + wrow + 15;
        if (!skip) {
            const uint32_t kbase = ks0 + (t % 3) * stageB;
            const uint32_t vbase = kbase + HTILE * 2;

            float sacc[8][4];
#pragma unroll
            for (int nt = 0; nt < 8; nt++)
#pragma unroll
                for (int r = 0; r < 4; r++) sacc[nt][r] = 0.0f;

#pragma unroll
            for (int ks = 0; ks < 4; ks++) {
                const uint32_t kb = (uint32_t)(ks * 32);
                uint32_t bf[8][2];
#pragma unroll
                for (int j = 0; j < 4; j++)
                    ldsm_x4(bf[2 * j][0], bf[2 * j][1], bf[2 * j + 1][0], bf[2 * j + 1][1],
                            kbase + ((j * 16 + brow) * VROW + bcol) * 2 + kb);
#pragma unroll
                for (int nt = 0; nt < 8; nt++)
                    mma_f16(sacc[nt], qf[ks], bf[nt]);
            }

            if (kt + 63 > q0 + wrow) {
#pragma unroll
                for (int nt = 0; nt < 8; nt++) {
                    const int c = kt + nt * 8 + 2 * tg;
                    if (c > r0g)     sacc[nt][0] = -1e30f;
                    if (c + 1 > r0g) sacc[nt][1] = -1e30f;
                    if (c > r1g)     sacc[nt][2] = -1e30f;
                    if (c + 1 > r1g) sacc[nt][3] = -1e30f;
                }
            }

            float rmax0 = -1e30f, rmax1 = -1e30f;
#pragma unroll
            for (int nt = 0; nt < 8; nt++) {
                rmax0 = fmaxf(rmax0, fmaxf(sacc[nt][0], sacc[nt][1]));
                rmax1 = fmaxf(rmax1, fmaxf(sacc[nt][2], sacc[nt][3]));
            }
            rmax0 = fmaxf(rmax0, __shfl_xor_sync(0xffffffff, rmax0, 1));
            rmax0 = fmaxf(rmax0, __shfl_xor_sync(0xffffffff, rmax0, 2));
            rmax1 = fmaxf(rmax1, __shfl_xor_sync(0xffffffff, rmax1, 1));
            rmax1 = fmaxf(rmax1, __shfl_xor_sync(0xffffffff, rmax1, 2));

            const float mn0 = fmaxf(mrow[0], rmax0);
            const float mn1 = fmaxf(mrow[1], rmax1);
            const float corr0 = __expf(mrow[0] - mn0);
            const float corr1 = __expf(mrow[1] - mn1);
            mrow[0] = mn0; mrow[1] = mn1;

            float rs0 = 0.0f, rs1 = 0.0f;
            __half* p0row = Ps + (wrow + g) * VROW + 2 * tg;
            __half* p1row = Ps + (wrow + g + 8) * VROW + 2 * tg;
#pragma unroll
            for (int nt = 0; nt < 8; nt++) {
                const float e0 = __expf(sacc[nt][0] - mn0);
                const float e1 = __expf(sacc[nt][1] - mn0);
                const float e2 = __expf(sacc[nt][2] - mn1);
                const float e3 = __expf(sacc[nt][3] - mn1);
                rs0 += e0 + e1;
                rs1 += e2 + e3;
                *reinterpret_cast<__half2*>(p0row + nt * 8) = __floats2half2_rn(e0, e1);
                *reinterpret_cast<__half2*>(p1row + nt * 8) = __floats2half2_rn(e2, e3);
            }
            rs0 += __shfl_xor_sync(0xffffffff, rs0, 1);
            rs0 += __shfl_xor_sync(0xffffffff, rs0, 2);
            rs1 += __shfl_xor_sync(0xffffffff, rs1, 1);
            rs1 += __shfl_xor_sync(0xffffffff, rs1, 2);
            lrow[0] = lrow[0] * corr0 + rs0;
            lrow[1] = lrow[1] * corr1 + rs1;

#pragma unroll
            for (int nt = 0; nt < 8; nt++) {
                of[nt][0] *= corr0; of[nt][1] *= corr0;
                of[nt][2] *= corr1; of[nt][3] *= corr1;
            }
            __syncwarp();

#pragma unroll
            for (int ks = 0; ks < 4; ks++) {
                uint32_t a[4];
                ldsm_x4(a[0], a[1], a[2], a[3],
                        psbase + ((wrow + arow) * VROW + acol + ks * 16) * 2);
                const uint32_t lrowaddr = vbase + ((ks * 16 + (lane & 15)) * VROW) * 2;
#pragma unroll
                for (int nt = 0; nt < 8; nt++) {
                    uint32_t bf2[2];
                    ldsm_x2_trans(bf2[0], bf2[1], lrowaddr + nt * 16);
                    mma_f16(of[nt], a, bf2);
                }
            }
        }
    }

    const float inv0 = 1.0f / lrow[0];
    const float inv1 = 1.0f / lrow[1];
    __half* o0 = O + (((size_t)b * SEQ + r0g) * NHEAD + h) * HDIM;
    __half* o1 = O + (((size_t)b * SEQ + r1g) * NHEAD + h) * HDIM;
#pragma unroll
    for (int nt = 0; nt < 8; nt++) {
        const int col = nt * 8 + 2 * tg;
        *reinterpret_cast<__half2*>(o0 + col) =
            __floats2half2_rn(of[nt][0] * inv0, of[nt][1] * inv0);
        *reinterpret_cast<__half2*>(o1 + col) =
            __floats2half2_rn(of[nt][2] * inv1, of[nt][3] * inv1);
    }
}

// ---------------------------------------------------------------------------
// kernel_launch
// ---------------------------------------------------------------------------
extern "C" void kernel_launch(void* const* d_in, const int* in_sizes, int n_in,
                              void* d_out, int out_size) {
    const float* x     = (const float*)d_in[0];
    const float* freqs = (const float*)d_in[1];
    const float* Wq    = (const float*)d_in[2];
    const float* Wk    = (const float*)d_in[3];
    const float* Wv    = (const float*)d_in[4];
    const float* Wo    = (const float*)d_in[5];
    float* out = (float*)d_out;

    __half *qh = nullptr, *kh = nullptr, *vh = nullptr;
    __half *attnh = nullptr, *xh = nullptr, *wh = nullptr;
    cudaGetSymbolAddress((void**)&qh,    g_qh);
    cudaGetSymbolAddress((void**)&kh,    g_kh);
    cudaGetSymbolAddress((void**)&vh,    g_vh);
    cudaGetSymbolAddress((void**)&attnh, g_attnh);
    cudaGetSymbolAddress((void**)&xh,    g_xh);
    cudaGetSymbolAddress((void**)&wh,    g_wh);

    cudaFuncSetAttribute(gemm_qkv,  cudaFuncAttributeMaxDynamicSharedMemorySize, GH_SMEM_BYTES);
    cudaFuncSetAttribute(gemm_proj, cudaFuncAttributeMaxDynamicSharedMemorySize, GH_SMEM_BYTES);
    cudaFuncSetAttribute(flash_attn_mma, cudaFuncAttributeMaxDynamicSharedMemorySize, HSMEM_BYTES);

    {
        const long long total = (long long)MROWS * CMODEL + 4LL * CMODEL * CMODEL;
        const int blocks = (int)(total / (256 * 8));
        to_half_all<<<blocks, 256>>>(x, Wq, Wk, Wv, Wo, xh, wh);
    }

    gemm_qkv<<<dim3(24, MROWS / 128), 128, GH_SMEM_BYTES>>>(xh, wh, qh, kh, vh, freqs);

    {
        dim3 agrid(SEQ / 128, NHEAD, BATCH);
        flash_attn_mma<<<agrid, 256, HSMEM_BYTES>>>(qh, kh, vh, attnh);
    }

    gemm_proj<<<dim3(CMODEL / 128, MROWS / 128), 128, GH_SMEM_BYTES>>>(attnh, wh, out);
}